// round 1
// baseline (speedup 1.0000x reference)
#include <cuda_runtime.h>
#include <math.h>

#define NN 207
#define BB 32
#define TT 12
#define CC 2
#define HORZ 12
#define DID 64
#define HH 128
#define CONCATN 2560          // DID + TT + NN*TT
#define MROWS (BB*NN*CC)      // 13248
#define BNCNT (BB*NN)         // 6624
#define EPSILON_V 10.0f
#define EPS_V 1e-8f

// ---------------- scratch (device globals; no allocation) ----------------
__device__ float g_X[(size_t)MROWS * CONCATN];   // (b,n,c, CONCAT)  ~136MB
__device__ float g_H0[MROWS * HH];
__device__ float g_H1[MROWS * HH];
__device__ float g_F[MROWS * HORZ];              // (b,n,c, HOR)
__device__ float g_hin[BNCNT * TT * CC];         // h_in
__device__ float g_level[BNCNT * CC];
__device__ float g_tgf[BNCNT * HORZ];
__device__ float g_dp[NN * NN];

// ---------------- time gates + h_in + level ----------------
__global__ void timegate_kernel(const float* __restrict__ hist,
                                const float* __restrict__ tod,
                                const float* __restrict__ emb,
                                const float* __restrict__ w1, const float* __restrict__ b1,
                                const float* __restrict__ w2, const float* __restrict__ b2,
                                const float* __restrict__ w3, const float* __restrict__ b3) {
    int bn = blockIdx.x;
    int n = bn % NN;
    __shared__ float sin_[DID + TT];
    __shared__ float stg[HH];
    __shared__ float stgb[TT];
    __shared__ float shin[TT * CC];
    int t = threadIdx.x;  // 128
    if (t < DID) sin_[t] = emb[n * DID + t];
    else if (t < DID + TT) sin_[t] = tod[bn * TT + (t - DID)];
    __syncthreads();
    float acc = b1[t];
#pragma unroll 4
    for (int i = 0; i < DID + TT; i++) acc += sin_[i] * w1[i * HH + t];
    stg[t] = fmaxf(acc, 0.f);
    __syncthreads();
    if (t < HORZ) {
        float a2 = b2[t], a3 = b3[t];
#pragma unroll 8
        for (int h = 0; h < HH; h++) {
            float v = stg[h];
            a2 += v * w2[h * HORZ + t];
            a3 += v * w3[h * TT + t];
        }
        g_tgf[bn * HORZ + t] = a2;
        stgb[t] = a3;
    }
    __syncthreads();
    if (t < TT * CC) {
        int tt = t >> 1, c = t & 1;
        float hv = hist[((size_t)bn * TT + tt) * CC + c] / (1.f + stgb[tt]);
        shin[t] = hv;
        g_hin[bn * TT * CC + t] = hv;
    }
    __syncthreads();
    if (t < CC) {
        float mx = -1e30f;
#pragma unroll
        for (int tt = 0; tt < TT; tt++) mx = fmaxf(mx, shin[tt * CC + t]);
        g_level[bn * CC + t] = mx;
    }
}

// ---------------- pairwise affinities ----------------
__global__ void dp_kernel(const float* __restrict__ emb) {
    int idx = blockIdx.x * blockDim.x + threadIdx.x;
    if (idx >= NN * NN) return;
    int i = idx / NN, j = idx % NN;
    float s = 0.f;
#pragma unroll 8
    for (int k = 0; k < DID; k++) s += emb[i * DID + k] * emb[j * DID + k];
    g_dp[idx] = expf(EPSILON_V * s);
}

// ---------------- build X = hist (b,n,c,CONCAT) ----------------
__global__ void build_hist_kernel(const float* __restrict__ emb) {
    int bn = blockIdx.x;
    int b = bn / NN, n = bn % NN;
    __shared__ float sh[NN * TT * CC];   // 4968 floats: all nodes' h_in for this batch
    __shared__ float sdp[NN];
    __shared__ float slvl[CC];
    int tid = threadIdx.x;
    for (int i = tid; i < NN * TT * CC; i += blockDim.x) sh[i] = g_hin[b * NN * TT * CC + i];
    for (int i = tid; i < NN; i += blockDim.x) sdp[i] = g_dp[n * NN + i];
    if (tid < CC) slvl[tid] = g_level[bn * CC + tid];
    __syncthreads();
    float lv0 = slvl[0], lv1 = slvl[1];
    float rl0 = 1.f / (lv0 + EPS_V), rl1 = 1.f / (lv1 + EPS_V);
    for (int idx = tid; idx < CC * CONCATN; idx += blockDim.x) {
        int c = idx / CONCATN;
        int k = idx - c * CONCATN;
        float lv = c ? lv1 : lv0;
        float rl = c ? rl1 : rl0;
        float val;
        if (k < TT) {
            val = sh[(n * TT + k) * CC + c] * rl;                 // history / level
        } else if (k < TT + NN * TT) {
            int m = k - TT;                                        // m = src*TT + t
            float a = sh[m * CC + c] * sdp[m / TT];
            val = fmaxf((a - lv) * rl, 0.f);
        } else {
            val = emb[n * DID + (k - TT - NN * TT)];
        }
        g_X[((size_t)bn * CC + c) * CONCATN + k] = val;
    }
}

// ---------------- generic tiled SGEMM with epilogues ----------------
// C(M x Nout) = epilogue(A(M x K) @ B(K x Nout) + bias)
// EPI: 0 = relu store, 1 = residual: Cout = relu(Cout - (acc+bias)) (in-place),
//      2 = plain store, 3 = accumulate (+=)
#define BM 64
#define BN 64
#define BKK 16

template <int EPI>
__global__ void sgemm_kernel(const float* __restrict__ A, const float* __restrict__ Bw,
                             const float* __restrict__ bias, float* __restrict__ Cout,
                             int M, int Nout, int K) {
    __shared__ float As[BKK][BM + 4];   // A transposed, padded row = 68 floats (16B-mult)
    __shared__ float Bs[BKK][BN];
    int m0 = blockIdx.x * BM;
    int n0 = blockIdx.y * BN;
    int tid = threadIdx.x;              // 256
    int tx = tid & 15, ty = tid >> 4;
    float acc[4][4] = {};

    int arow = tid >> 2;                // 0..63
    int ac4 = (tid & 3) * 4;            // 0,4,8,12
    int bk = tid >> 4;                  // 0..15
    int bn4 = (tid & 15) * 4;           // 0..60
    const bool nfull = (n0 + BN <= Nout);

    for (int k0 = 0; k0 < K; k0 += BKK) {
        float4 av = *reinterpret_cast<const float4*>(&A[(size_t)(m0 + arow) * K + k0 + ac4]);
        As[ac4 + 0][arow] = av.x;
        As[ac4 + 1][arow] = av.y;
        As[ac4 + 2][arow] = av.z;
        As[ac4 + 3][arow] = av.w;
        if (nfull) {
            float4 bv = *reinterpret_cast<const float4*>(&Bw[(size_t)(k0 + bk) * Nout + n0 + bn4]);
            *reinterpret_cast<float4*>(&Bs[bk][bn4]) = bv;
        } else {
#pragma unroll
            for (int j = 0; j < 4; j++) {
                int nc = n0 + bn4 + j;
                Bs[bk][bn4 + j] = (nc < Nout) ? Bw[(size_t)(k0 + bk) * Nout + nc] : 0.f;
            }
        }
        __syncthreads();
#pragma unroll
        for (int k = 0; k < BKK; k++) {
            float4 a4 = *reinterpret_cast<const float4*>(&As[k][ty * 4]);
            float4 b4 = *reinterpret_cast<const float4*>(&Bs[k][tx * 4]);
            float a[4] = {a4.x, a4.y, a4.z, a4.w};
            float b[4] = {b4.x, b4.y, b4.z, b4.w};
#pragma unroll
            for (int i = 0; i < 4; i++)
#pragma unroll
                for (int j = 0; j < 4; j++) acc[i][j] += a[i] * b[j];
        }
        __syncthreads();
    }

#pragma unroll
    for (int i = 0; i < 4; i++) {
        int row = m0 + ty * 4 + i;
#pragma unroll
        for (int j = 0; j < 4; j++) {
            int col = n0 + tx * 4 + j;
            if (col < Nout) {
                float v = acc[i][j] + bias[col];
                size_t off = (size_t)row * Nout + col;
                if (EPI == 0) Cout[off] = fmaxf(v, 0.f);
                else if (EPI == 1) Cout[off] = fmaxf(Cout[off] - v, 0.f);
                else if (EPI == 2) Cout[off] = v;
                else Cout[off] += v;
            }
        }
    }
}

// ---------------- outputs ----------------
__global__ void backcast_out_kernel(float* __restrict__ out) {
    int bn = blockIdx.x;
    const float* x0 = &g_X[(size_t)bn * CC * CONCATN];
    float2* o = reinterpret_cast<float2*>(out) + (size_t)bn * CONCATN;
    for (int k = threadIdx.x; k < CONCATN; k += blockDim.x) {
        float2 v;
        v.x = x0[k];
        v.y = x0[CONCATN + k];
        o[k] = v;
    }
}

__global__ void forecast_out_kernel(float* __restrict__ out) {
    int idx = blockIdx.x * blockDim.x + threadIdx.x;
    if (idx >= BNCNT * HORZ * CC) return;
    int c = idx & 1;
    int h = (idx >> 1) % HORZ;
    int bn = idx / (HORZ * CC);
    float v = g_F[((size_t)bn * CC + c) * HORZ + h];
    v *= g_level[bn * CC + c];
    v *= (1.f + g_tgf[bn * HORZ + h]);
    out[idx] = v;
}

// ---------------- launcher ----------------
extern "C" void kernel_launch(void* const* d_in, const int* in_sizes, int n_in,
                              void* d_out, int out_size) {
    const float* history = (const float*)d_in[0];
    const float* tod     = (const float*)d_in[1];
    const float* emb     = (const float*)d_in[2];
    const float* tg1_w = (const float*)d_in[3];
    const float* tg1_b = (const float*)d_in[4];
    const float* tg2_w = (const float*)d_in[5];
    const float* tg2_b = (const float*)d_in[6];
    const float* tg3_w = (const float*)d_in[7];
    const float* tg3_b = (const float*)d_in[8];
    const float* fc0_w = (const float*)d_in[9];
    const float* fc0_b = (const float*)d_in[10];
    const float* fc_w  = (const float*)d_in[11];
    const float* fc_b  = (const float*)d_in[12];
    const float* fore_w = (const float*)d_in[13];
    const float* fore_b = (const float*)d_in[14];
    const float* back_w = (const float*)d_in[15];
    const float* back_b = (const float*)d_in[16];
    float* out = (float*)d_out;

    float *pX, *pH0, *pH1, *pF;
    cudaGetSymbolAddress((void**)&pX, g_X);
    cudaGetSymbolAddress((void**)&pH0, g_H0);
    cudaGetSymbolAddress((void**)&pH1, g_H1);
    cudaGetSymbolAddress((void**)&pF, g_F);

    timegate_kernel<<<BNCNT, 128>>>(history, tod, emb, tg1_w, tg1_b, tg2_w, tg2_b, tg3_w, tg3_b);
    dp_kernel<<<(NN * NN + 255) / 256, 256>>>(emb);
    build_hist_kernel<<<BNCNT, 256>>>(emb);

    for (int i = 0; i < 3; i++) {
        const float* w0 = fc0_w + (size_t)i * CONCATN * HH;
        const float* b0 = fc0_b + i * HH;
        sgemm_kernel<0><<<dim3(MROWS / BM, HH / BN), 256>>>(pX, w0, b0, pH0, MROWS, HH, CONCATN);
        sgemm_kernel<0><<<dim3(MROWS / BM, HH / BN), 256>>>(
            pH0, fc_w + ((size_t)i * 2 + 0) * HH * HH, fc_b + (i * 2 + 0) * HH, pH1, MROWS, HH, HH);
        sgemm_kernel<0><<<dim3(MROWS / BM, HH / BN), 256>>>(
            pH1, fc_w + ((size_t)i * 2 + 1) * HH * HH, fc_b + (i * 2 + 1) * HH, pH0, MROWS, HH, HH);
        if (i == 0)
            sgemm_kernel<2><<<dim3(MROWS / BM, 1), 256>>>(
                pH0, fore_w + (size_t)i * HH * HORZ, fore_b + i * HORZ, pF, MROWS, HORZ, HH);
        else
            sgemm_kernel<3><<<dim3(MROWS / BM, 1), 256>>>(
                pH0, fore_w + (size_t)i * HH * HORZ, fore_b + i * HORZ, pF, MROWS, HORZ, HH);
        sgemm_kernel<1><<<dim3(MROWS / BM, CONCATN / BN), 256>>>(
            pH0, back_w + (size_t)i * HH * CONCATN, back_b + (size_t)i * CONCATN, pX, MROWS, CONCATN, HH);
    }

    backcast_out_kernel<<<BNCNT, 256>>>(out);
    forecast_out_kernel<<<(BNCNT * HORZ * CC + 255) / 256, 256>>>(out + (size_t)MROWS * CONCATN);
}